// round 1
// baseline (speedup 1.0000x reference)
#include <cuda_runtime.h>

#define NN 50000
#define NE 800000
#define D  128
#define KC 32      // k-chunk staged in smem
#define ROWS 32    // node rows per block in transform

// Scratch: transformed features y = x @ W^T   (25.6 MB)
__device__ float g_y[NN * D];

// ---------------------------------------------------------------------------
// Kernel 1: y = x @ W^T.   W is [D_OUT, D_IN] row-major; y[n][o] = sum_k x[n][k]*W[o][k]
// Block: 128 threads -> 32 nodes x 128 outputs. Thread owns 8 rows x 4 cols.
// W and x chunks staged TRANSPOSED in smem so the inner loop is
// 1 LDS.128 (w) + 2 broadcast LDS.128 (x) per 32 FFMA.
// ---------------------------------------------------------------------------
__global__ __launch_bounds__(128) void transform_kernel(
    const float* __restrict__ x, const float* __restrict__ W)
{
    __shared__ float Wsm[KC][D + 4];     // [k][out_col], pad 4 -> 16B-aligned rows, conflict-free
    __shared__ float xs [KC][ROWS + 4];  // [k][node_row]

    const int t    = threadIdx.x;
    const int base = blockIdx.x * ROWS;
    const int c0   = (t & 31) * 4;   // output column group (lane)
    const int r0   = (t >> 5) * 8;   // node row group (warp)

    float acc[8][4];
#pragma unroll
    for (int i = 0; i < 8; i++)
#pragma unroll
        for (int j = 0; j < 4; j++) acc[i][j] = 0.f;

#pragma unroll 1
    for (int kc = 0; kc < D; kc += KC) {
        __syncthreads();
        // Load W chunk transposed: Wsm[k][col] = W[col][kc+k]
#pragma unroll
        for (int i = t * 4; i < D * KC; i += 128 * 4) {
            int row = i / KC;           // output col in W
            int cc  = i % KC;           // k within chunk
            float4 v = *reinterpret_cast<const float4*>(&W[row * D + kc + cc]);
            Wsm[cc + 0][row] = v.x;
            Wsm[cc + 1][row] = v.y;
            Wsm[cc + 2][row] = v.z;
            Wsm[cc + 3][row] = v.w;
        }
        // Load x chunk transposed: xs[k][r] = x[base+r][kc+k]
#pragma unroll
        for (int i = t * 4; i < ROWS * KC; i += 128 * 4) {
            int r  = i / KC;
            int cc = i % KC;
            float4 v = make_float4(0.f, 0.f, 0.f, 0.f);
            if (base + r < NN)
                v = *reinterpret_cast<const float4*>(&x[(base + r) * D + kc + cc]);
            xs[cc + 0][r] = v.x;
            xs[cc + 1][r] = v.y;
            xs[cc + 2][r] = v.z;
            xs[cc + 3][r] = v.w;
        }
        __syncthreads();

#pragma unroll
        for (int k = 0; k < KC; k++) {
            float4 wv = *reinterpret_cast<const float4*>(&Wsm[k][c0]);
            float4 xa = *reinterpret_cast<const float4*>(&xs[k][r0]);      // broadcast
            float4 xb = *reinterpret_cast<const float4*>(&xs[k][r0 + 4]);  // broadcast
            float xv[8] = {xa.x, xa.y, xa.z, xa.w, xb.x, xb.y, xb.z, xb.w};
            float wc[4] = {wv.x, wv.y, wv.z, wv.w};
#pragma unroll
            for (int ri = 0; ri < 8; ri++)
#pragma unroll
                for (int ci = 0; ci < 4; ci++)
                    acc[ri][ci] += xv[ri] * wc[ci];
        }
    }

#pragma unroll
    for (int ri = 0; ri < 8; ri++) {
        int node = base + r0 + ri;
        if (node < NN) {
            float4 v = make_float4(acc[ri][0], acc[ri][1], acc[ri][2], acc[ri][3]);
            *reinterpret_cast<float4*>(&g_y[node * D + c0]) = v;
        }
    }
}

// ---------------------------------------------------------------------------
// Kernel 2: out[i][d] = b[d]  (bias broadcast; output then scatter-accumulated)
// ---------------------------------------------------------------------------
__global__ void init_out_kernel(float4* __restrict__ out, const float* __restrict__ b)
{
    int i = blockIdx.x * blockDim.x + threadIdx.x;
    if (i >= NN * (D / 4)) return;
    int d4 = i & (D / 4 - 1);  // i % 32
    float4 v = *reinterpret_cast<const float4*>(&b[d4 * 4]);
    out[i] = v;
}

// ---------------------------------------------------------------------------
// Kernel 3: out[row[e]] += w[e] * y[col[e]]  — one warp per edge,
// each lane handles 4 floats via red.global.add.v4.f32 (4x fewer atomics).
// ---------------------------------------------------------------------------
__global__ __launch_bounds__(256) void scatter_kernel(
    const int*   __restrict__ erow,
    const int*   __restrict__ ecol,
    const float* __restrict__ ew,
    float*       __restrict__ out)
{
    int gtid = blockIdx.x * blockDim.x + threadIdx.x;
    int e    = gtid >> 5;
    int lane = threadIdx.x & 31;
    if (e >= NE) return;

    int   r  = __ldg(&erow[e]);
    int   c  = __ldg(&ecol[e]);
    float w  = __ldg(&ew[e]);

    float4 v = *reinterpret_cast<const float4*>(&g_y[c * D + lane * 4]);
    float4 m = make_float4(v.x * w, v.y * w, v.z * w, v.w * w);

    float* dst = &out[r * D + lane * 4];
    asm volatile("red.global.add.v4.f32 [%0], {%1, %2, %3, %4};"
                 :: "l"(dst), "f"(m.x), "f"(m.y), "f"(m.z), "f"(m.w)
                 : "memory");
}

// ---------------------------------------------------------------------------
extern "C" void kernel_launch(void* const* d_in, const int* in_sizes, int n_in,
                              void* d_out, int out_size)
{
    const float* x    = (const float*)d_in[0];
    const int*   erow = (const int*)  d_in[1];
    const int*   ecol = (const int*)  d_in[2];
    const float* ew   = (const float*)d_in[3];
    const float* W    = (const float*)d_in[4];
    const float* b    = (const float*)d_in[5];
    float*       out  = (float*)d_out;

    // y = x @ W^T
    transform_kernel<<<(NN + ROWS - 1) / ROWS, 128>>>(x, W);
    // out = b (broadcast)
    init_out_kernel<<<(NN * (D / 4) + 255) / 256, 256>>>((float4*)out, b);
    // out[row] += w * y[col]
    scatter_kernel<<<(NE * 32 + 255) / 256, 256>>>(erow, ecol, ew, out);
}